// round 12
// baseline (speedup 1.0000x reference)
#include <cuda_runtime.h>
#include <cuda_fp16.h>
#include <cstdint>

#define NB 8
#define NC 64
#define NH 256
#define NW 512
#define NK 9
#define HW (NH * NW)                // 131,072
#define BHW (NB * NH * NW)          // 1,048,576

typedef unsigned long long ull;

// Scratch: P[k][b][y][x] = sum_c W[c,k] * F[b,c,y,x]   (fp16: 18.9 MB, L2-resident)
__device__ __half g_P[(size_t)NK * BHW];

// Packed f32x2 FMA (sm_100+): d = a*b + c on two lanes at once.
#define FMA_F32X2(d, a, b, c) \
    asm("fma.rn.f32x2 %0, %1, %2, %3;" : "=l"(d) : "l"(a), "l"(b), "l"(c))

__device__ __forceinline__ void cp16(uint32_t dst, const void* src) {
    asm volatile("cp.async.cg.shared.global [%0], [%1], 16;" :: "r"(dst), "l"(src));
}
__device__ __forceinline__ void cpcommit() {
    asm volatile("cp.async.commit_group;");
}
template <int N> __device__ __forceinline__ void cpwait() {
    asm volatile("cp.async.wait_group %0;" :: "n"(N));
}

// ---------------------------------------------------------------------------
// Pass 1: channel reduction, cp.async-pipelined (R8 config: best measured).
// One block per (b,y) row. 64 channels in 8 chunks of 8; 4-stage smem ring
// (16 KB/stage, 64 KB dynamic). Each thread owns 2 consecutive x.
// ---------------------------------------------------------------------------
__global__ void __launch_bounds__(256) pass1_kernel(
    const float* __restrict__ feature,   // [B, C, H, W]
    const float* __restrict__ weight)    // [1, C, 3, 3] -> [C, 9]
{
    extern __shared__ float buf[];       // [4 stages][8 ch][512 x] = 65536 B
    __shared__ float4 sw4[NK][NC / 2];   // {w_c,w_c,w_c1,w_c1} per (k, pair)

    const int t = threadIdx.x;

    for (int i = t; i < NK * (NC / 2); i += 256) {
        int k  = i % NK;
        int cc = i / NK;
        float w0 = weight[(2 * cc + 0) * NK + k];
        float w1 = weight[(2 * cc + 1) * NK + k];
        sw4[k][cc] = make_float4(w0, w0, w1, w1);
    }

    const int yb = blockIdx.x;           // b*NH + y
    const float* frow = feature
        + (size_t)(yb / NH) * NC * HW + (size_t)(yb % NH) * NW;

    const uint32_t sbase = (uint32_t)__cvta_generic_to_shared(buf);

    // Fill stage s with chunk (8 channels): 1024 x 16B, 4 copies per thread.
#define FILL(s, chunk)                                                        \
    do {                                                                      \
        const float* src0 = frow + (size_t)((chunk) * 8) * HW;                \
        _Pragma("unroll")                                                     \
        for (int i = 0; i < 4; ++i) {                                         \
            int idx = t + i * 256;       /* 0..1023 */                        \
            int cc  = idx >> 7;          /* channel within chunk */           \
            int q   = idx & 127;         /* 16B unit within row */            \
            cp16(sbase + (uint32_t)((s) * 16384 + cc * 2048 + q * 16),        \
                 src0 + (size_t)cc * HW + q * 4);                             \
        }                                                                     \
        cpcommit();                                                           \
    } while (0)

    ull acc[NK];
#pragma unroll
    for (int k = 0; k < NK; ++k) acc[k] = 0ull;

    // Prologue: 3 stages in flight.
    FILL(0, 0);
    FILL(1, 1);
    FILL(2, 2);
    __syncthreads();                     // also publishes sw4

#pragma unroll
    for (int chunk = 0; chunk < 8; ++chunk) {
        // Allow pending = min(2, 7 - chunk) so chunk's stage is complete.
        if (chunk < 6)       cpwait<2>();
        else if (chunk == 6) cpwait<1>();
        else                 cpwait<0>();
        __syncthreads();                 // cross-thread visibility of stage

        const float* st = buf + (chunk & 3) * 4096;
#pragma unroll
        for (int p = 0; p < 4; ++p) {    // channel pairs within chunk
            ull f0 = *(const ull*)(st + (2 * p + 0) * 512 + 2 * t);
            ull f1 = *(const ull*)(st + (2 * p + 1) * 512 + 2 * t);
            int cidx = chunk * 4 + p;    // global pair index 0..31
#pragma unroll
            for (int k = 0; k < NK; ++k) {
                ulonglong2 wp = *(const ulonglong2*)&sw4[k][cidx];
                FMA_F32X2(acc[k], f0, wp.x, acc[k]);
                FMA_F32X2(acc[k], f1, wp.y, acc[k]);
            }
        }
        __syncthreads();                 // all consumers done before refill
        if (chunk + 3 < 8) FILL((chunk + 3) & 3, chunk + 3);
    }
#undef FILL

    // Store: thread owns x = {2t, 2t+1}; one 4B half2 store per tap.
    size_t pbase = (size_t)yb * NW + 2 * t;
#pragma unroll
    for (int k = 0; k < NK; ++k) {
        float2 v = *(float2*)&acc[k];
        __half2 h = __floats2half2_rn(v.x, v.y);
        *(__half2*)(g_P + (size_t)k * BHW + pbase) = h;
    }
}

// ---------------------------------------------------------------------------
// Pass 2: cyclic-shift gather + 2x2 upsample.
// Identity (validated R11): gj[h,w,k] = (w + s[h,k]) % W with s = gj[h,0,k],
// gi[h,w,k] = gi[h,0,k]. Thread = 4 consecutive w for one b; block = (h,
// quarter row) x 8 b. 18 broadcast index ints per block. Full occupancy.
// ---------------------------------------------------------------------------
__global__ void __launch_bounds__(256, 4) pass2_kernel(
    const int* __restrict__ gi,    // [H, W, 9]
    const int* __restrict__ gj,    // [H, W, 9]
    float* __restrict__ out)       // [B, 1, 2H, 2W]
{
    const int h = blockIdx.y;
    const int t = threadIdx.x;
    const int b  = t >> 5;                           // 0..7
    const int w0 = blockIdx.x * 128 + (t & 31) * 4;  // 0..508

    const int* ri = gi + (size_t)h * NW * NK;        // row h, w=0
    const int* rj = gj + (size_t)h * NW * NK;

    int ys[NK], ss[NK];
#pragma unroll
    for (int k = 0; k < NK; ++k) ys[k] = ri[k];
#pragma unroll
    for (int k = 0; k < NK; ++k) ss[k] = rj[k];

    // Stage all 36 u16 gathers (independent -> deep MLP), then reduce.
    unsigned short v[NK][4];
#pragma unroll
    for (int k = 0; k < NK; ++k) {
        const unsigned short* row = (const unsigned short*)g_P
            + (size_t)k * BHW + ((size_t)b * NH + ys[k]) * NW;
        int base = w0 + ss[k];
#pragma unroll
        for (int j = 0; j < 4; ++j)
            v[k][j] = row[(base + j) & (NW - 1)];
    }

    float acc[4] = {0.f, 0.f, 0.f, 0.f};
#pragma unroll
    for (int k = 0; k < NK; ++k)
#pragma unroll
        for (int j = 0; j < 4; ++j)
            acc[j] += __half2float(__ushort_as_half(v[k][j]));

    // 2x2 upsample: 4 outputs -> 8 floats per row, two rows. Evict-first.
    float* orow = out + ((size_t)b * (2 * NH) + 2 * h) * (2 * NW) + 2 * w0;
#pragma unroll
    for (int i = 0; i < 2; ++i) {
        float4 q = make_float4(acc[2 * i], acc[2 * i],
                               acc[2 * i + 1], acc[2 * i + 1]);
        asm volatile("st.global.cs.v4.f32 [%0], {%1, %2, %3, %4};"
                     :: "l"(orow + 4 * i), "f"(q.x), "f"(q.y), "f"(q.z), "f"(q.w));
        asm volatile("st.global.cs.v4.f32 [%0], {%1, %2, %3, %4};"
                     :: "l"(orow + 2 * NW + 4 * i),
                        "f"(q.x), "f"(q.y), "f"(q.z), "f"(q.w));
    }
}

// ---------------------------------------------------------------------------
// Launch: graph-capturable, allocation-free.
// Inputs (metadata order): feature f32, weight f32, gi i32, gj i32.
// ---------------------------------------------------------------------------
extern "C" void kernel_launch(void* const* d_in, const int* in_sizes, int n_in,
                              void* d_out, int out_size)
{
    const float* feature = (const float*)d_in[0];
    const float* weight  = (const float*)d_in[1];
    const int*   gi      = (const int*)d_in[2];
    const int*   gj      = (const int*)d_in[3];
    float*       out     = (float*)d_out;

    // 64 KB dynamic smem opt-in (idempotent host call).
    static bool attr_set = false;
    if (!attr_set) {
        cudaFuncSetAttribute(pass1_kernel,
                             cudaFuncAttributeMaxDynamicSharedMemorySize, 65536);
        attr_set = true;
    }

    // Pass 1: one block per (b,y) row: 2048 blocks x 256 threads, 64KB smem
    pass1_kernel<<<NB * NH, 256, 65536>>>(feature, weight);
    // Pass 2: grid (4 quarter-rows, 256 h) x 256 threads
    dim3 g2(4, NH);
    pass2_kernel<<<g2, 256>>>(gi, gj, out);
}

// round 13
// speedup vs baseline: 1.5022x; 1.5022x over previous
#include <cuda_runtime.h>
#include <cuda_fp16.h>
#include <cstdint>

#define NB 8
#define NC 64
#define NH 256
#define NW 512
#define NK 9
#define HW (NH * NW)                // 131,072
#define BHW (NB * NH * NW)          // 1,048,576

typedef unsigned long long ull;

// Scratch: P[k][b][y][x] = sum_c W[c,k] * F[b,c,y,x]   (fp16: 18.9 MB, L2-resident)
__device__ __half g_P[(size_t)NK * BHW];

// Packed f32x2 FMA (sm_100+): d = a*b + c on two lanes at once.
#define FMA_F32X2(d, a, b, c) \
    asm("fma.rn.f32x2 %0, %1, %2, %3;" : "=l"(d) : "l"(a), "l"(b), "l"(c))

__device__ __forceinline__ void cp16(uint32_t dst, const void* src) {
    asm volatile("cp.async.cg.shared.global [%0], [%1], 16;" :: "r"(dst), "l"(src));
}
__device__ __forceinline__ void cpcommit() {
    asm volatile("cp.async.commit_group;");
}
template <int N> __device__ __forceinline__ void cpwait() {
    asm volatile("cp.async.wait_group %0;" :: "n"(N));
}

// ---------------------------------------------------------------------------
// Pass 1: channel reduction, cp.async-pipelined (R8 config: best measured).
// One block per (b,y) row. 64 channels in 8 chunks of 8; 4-stage smem ring
// (16 KB/stage, 64 KB dynamic). Each thread owns 2 consecutive x.
// ---------------------------------------------------------------------------
__global__ void __launch_bounds__(256) pass1_kernel(
    const float* __restrict__ feature,   // [B, C, H, W]
    const float* __restrict__ weight)    // [1, C, 3, 3] -> [C, 9]
{
    extern __shared__ float buf[];       // [4 stages][8 ch][512 x] = 65536 B
    __shared__ float4 sw4[NK][NC / 2];   // {w_c,w_c,w_c1,w_c1} per (k, pair)

    const int t = threadIdx.x;

    for (int i = t; i < NK * (NC / 2); i += 256) {
        int k  = i % NK;
        int cc = i / NK;
        float w0 = weight[(2 * cc + 0) * NK + k];
        float w1 = weight[(2 * cc + 1) * NK + k];
        sw4[k][cc] = make_float4(w0, w0, w1, w1);
    }

    const int yb = blockIdx.x;           // b*NH + y
    const float* frow = feature
        + (size_t)(yb / NH) * NC * HW + (size_t)(yb % NH) * NW;

    const uint32_t sbase = (uint32_t)__cvta_generic_to_shared(buf);

    // Fill stage s with chunk (8 channels): 1024 x 16B, 4 copies per thread.
#define FILL(s, chunk)                                                        \
    do {                                                                      \
        const float* src0 = frow + (size_t)((chunk) * 8) * HW;                \
        _Pragma("unroll")                                                     \
        for (int i = 0; i < 4; ++i) {                                         \
            int idx = t + i * 256;       /* 0..1023 */                        \
            int cc  = idx >> 7;          /* channel within chunk */           \
            int q   = idx & 127;         /* 16B unit within row */            \
            cp16(sbase + (uint32_t)((s) * 16384 + cc * 2048 + q * 16),        \
                 src0 + (size_t)cc * HW + q * 4);                             \
        }                                                                     \
        cpcommit();                                                           \
    } while (0)

    ull acc[NK];
#pragma unroll
    for (int k = 0; k < NK; ++k) acc[k] = 0ull;

    // Prologue: 3 stages in flight.
    FILL(0, 0);
    FILL(1, 1);
    FILL(2, 2);
    __syncthreads();                     // also publishes sw4

#pragma unroll
    for (int chunk = 0; chunk < 8; ++chunk) {
        // Allow pending = min(2, 7 - chunk) so chunk's stage is complete.
        if (chunk < 6)       cpwait<2>();
        else if (chunk == 6) cpwait<1>();
        else                 cpwait<0>();
        __syncthreads();                 // cross-thread visibility of stage

        const float* st = buf + (chunk & 3) * 4096;
#pragma unroll
        for (int p = 0; p < 4; ++p) {    // channel pairs within chunk
            ull f0 = *(const ull*)(st + (2 * p + 0) * 512 + 2 * t);
            ull f1 = *(const ull*)(st + (2 * p + 1) * 512 + 2 * t);
            int cidx = chunk * 4 + p;    // global pair index 0..31
#pragma unroll
            for (int k = 0; k < NK; ++k) {
                ulonglong2 wp = *(const ulonglong2*)&sw4[k][cidx];
                FMA_F32X2(acc[k], f0, wp.x, acc[k]);
                FMA_F32X2(acc[k], f1, wp.y, acc[k]);
            }
        }
        __syncthreads();                 // all consumers done before refill
        if (chunk + 3 < 8) FILL((chunk + 3) & 3, chunk + 3);
    }
#undef FILL

    // Store: thread owns x = {2t, 2t+1}; one 4B half2 store per tap.
    size_t pbase = (size_t)yb * NW + 2 * t;
#pragma unroll
    for (int k = 0; k < NK; ++k) {
        float2 v = *(float2*)&acc[k];
        __half2 h = __floats2half2_rn(v.x, v.y);
        *(__half2*)(g_P + (size_t)k * BHW + pbase) = h;
    }
}

// ---------------------------------------------------------------------------
// Pass 2 (R9 config: best measured). One thread per (h,w) x 4 batches;
// grid.y=2 covers the 8 batches. All 36 fp16 gathers explicitly staged into
// registers (128-reg budget) for full MLP, then reduced. Output written
// evict-first: its 67 MB write is this kernel's floor; keep L2 for P.
// ---------------------------------------------------------------------------
__global__ void __launch_bounds__(256, 2) pass2_kernel(
    const int* __restrict__ gi,    // [H, W, 9]
    const int* __restrict__ gj,    // [H, W, 9]
    float* __restrict__ out)       // [B, 1, 2H, 2W]
{
    int g = blockIdx.x * 256 + threadIdx.x;      // [0, H*W)
    int h = g / NW;
    int w = g % NW;
    int ib = g * NK;
    int b0 = blockIdx.y * 4;                      // batch group: 0 or 4

    int ys[NK], xs[NK];
#pragma unroll
    for (int k = 0; k < NK; ++k) ys[k] = gi[ib + k];
#pragma unroll
    for (int k = 0; k < NK; ++k) xs[k] = gj[ib + k];

    // Stage all 36 gathers (independent loads -> deep MLP).
    unsigned short v[NK][4];
#pragma unroll
    for (int k = 0; k < NK; ++k) {
        const unsigned short* Pk = (const unsigned short*)g_P + (size_t)k * BHW
                                 + ((size_t)b0 * NH + ys[k]) * NW + xs[k];
#pragma unroll
        for (int j = 0; j < 4; ++j)
            v[k][j] = Pk[(size_t)j * HW];
    }

    float acc[4] = {0.f, 0.f, 0.f, 0.f};
#pragma unroll
    for (int k = 0; k < NK; ++k)
#pragma unroll
        for (int j = 0; j < 4; ++j)
            acc[j] += __half2float(__ushort_as_half(v[k][j]));

    // out viewed as float2: [B][2H][NW]; evict-first stores (no reuse).
    float2* o2 = (float2*)out;
#pragma unroll
    for (int j = 0; j < 4; ++j) {
        float2 val = make_float2(acc[j], acc[j]);
        size_t row0 = ((size_t)(b0 + j) * (2 * NH) + 2 * h) * NW + w;
        asm volatile("st.global.cs.v2.f32 [%0], {%1, %2};"
                     :: "l"(o2 + row0), "f"(val.x), "f"(val.y));
        asm volatile("st.global.cs.v2.f32 [%0], {%1, %2};"
                     :: "l"(o2 + row0 + NW), "f"(val.x), "f"(val.y));
    }
}

// ---------------------------------------------------------------------------
// Launch: graph-capturable, allocation-free.
// Inputs (metadata order): feature f32, weight f32, gi i32, gj i32.
// ---------------------------------------------------------------------------
extern "C" void kernel_launch(void* const* d_in, const int* in_sizes, int n_in,
                              void* d_out, int out_size)
{
    const float* feature = (const float*)d_in[0];
    const float* weight  = (const float*)d_in[1];
    const int*   gi      = (const int*)d_in[2];
    const int*   gj      = (const int*)d_in[3];
    float*       out     = (float*)d_out;

    // 64 KB dynamic smem opt-in (idempotent host call).
    static bool attr_set = false;
    if (!attr_set) {
        cudaFuncSetAttribute(pass1_kernel,
                             cudaFuncAttributeMaxDynamicSharedMemorySize, 65536);
        attr_set = true;
    }

    // Pass 1: one block per (b,y) row: 2048 blocks x 256 threads, 64KB smem
    pass1_kernel<<<NB * NH, 256, 65536>>>(feature, weight);
    // Pass 2: thread per (h,w) x 4 batches; grid (512, 2) x 256
    dim3 g2(NH * NW / 256, 2);
    pass2_kernel<<<g2, 256>>>(gi, gj, out);
}